// round 1
// baseline (speedup 1.0000x reference)
#include <cuda_runtime.h>

// Mean-shift: N=9216 pixels, D=32 dims, 3 iterations.
//   K[i,j] = exp(bw * x_i . x_j);  deg_j = sum_i K[i,j]
//   Xnew[:,j] = eta/deg_j * sum_i K[i,j] x_i + (1-eta) x_j
// Fused attention-style: never materialize K.

#define NPTS    9216
#define DIM     32
#define DP      (DIM / 2)          // 16 float2 pairs
#define TILE_J  128
#define TILE_I  128
#define ISPLITS 8
#define JTILES  (NPTS / TILE_J)            // 72
#define KEYS_PER_SPLIT (NPTS / ISPLITS)    // 1152
#define ITILES  (KEYS_PER_SPLIT / TILE_I)  // 9
#define BW      2.0f
#define ETA     0.5f

// Scratch (no cudaMalloc allowed): partial accumulators per key-split.
__device__ float g_part_acc[ISPLITS][DIM][NPTS];  // ~9.4 MB
__device__ float g_part_deg[ISPLITS][NPTS];       // ~0.3 MB

// ---- packed f32x2 helpers (Blackwell FFMA2 path) ----
__device__ __forceinline__ unsigned long long pack2(float x, float y) {
    unsigned long long r;
    asm("mov.b64 %0, {%1, %2};" : "=l"(r) : "f"(x), "f"(y));
    return r;
}
__device__ __forceinline__ void unpack2(unsigned long long v, float& x, float& y) {
    asm("mov.b64 {%0, %1}, %2;" : "=f"(x), "=f"(y) : "l"(v));
}
__device__ __forceinline__ unsigned long long ffma2(unsigned long long a,
                                                    unsigned long long b,
                                                    unsigned long long c) {
    unsigned long long r;
    asm("fma.rn.f32x2 %0, %1, %2, %3;" : "=l"(r) : "l"(a), "l"(b), "l"(c));
    return r;
}

// Pad key rows to 34 floats: 136B stride keeps 8B alignment for LDS.64 and
// spreads write banks (2t+d mod 32 -> only 2-way write conflict).
#define KROW 34

__global__ void __launch_bounds__(TILE_J)
ms_partial(const float* __restrict__ X) {
    const int jt    = blockIdx.x;   // 0..71  (query tile)
    const int split = blockIdx.y;   // 0..7   (key split)
    const int t     = threadIdx.x;  // 0..127
    const int j     = jt * TILE_J + t;

    __shared__ float ks[TILE_I][KROW];

    // Query column j into registers as 16 packed pairs (coalesced loads).
    unsigned long long q[DP];
#pragma unroll
    for (int p = 0; p < DP; p++) {
        float a = X[(2 * p) * NPTS + j];
        float b = X[(2 * p + 1) * NPTS + j];
        q[p] = pack2(a, b);
    }

    unsigned long long acc[DP];
#pragma unroll
    for (int p = 0; p < DP; p++) acc[p] = 0ULL;  // (0.0f, 0.0f)
    float deg = 0.0f;

    const int ibase = split * KEYS_PER_SPLIT;
    for (int it = 0; it < ITILES; it++) {
        const int i0 = ibase + it * TILE_I;
        __syncthreads();
        // Thread t loads key column i0+t (coalesced across threads per d).
#pragma unroll
        for (int d = 0; d < DIM; d++)
            ks[t][d] = X[d * NPTS + i0 + t];
        __syncthreads();

#pragma unroll 4
        for (int i = 0; i < TILE_I; i++) {
            // Broadcast key i: 16x LDS.64 (conflict-free broadcast).
            const unsigned long long* krow =
                reinterpret_cast<const unsigned long long*>(&ks[i][0]);
            unsigned long long kd[DP];
#pragma unroll
            for (int p = 0; p < DP; p++) kd[p] = krow[p];

            // dot(x_i, x_j) via packed FMA
            unsigned long long dv = 0ULL;
#pragma unroll
            for (int p = 0; p < DP; p++) dv = ffma2(kd[p], q[p], dv);
            float dx, dy;
            unpack2(dv, dx, dy);

            const float k = __expf(BW * (dx + dy));
            deg += k;
            const unsigned long long kk = pack2(k, k);
#pragma unroll
            for (int p = 0; p < DP; p++) acc[p] = ffma2(kk, kd[p], acc[p]);
        }
    }

    // Write partials, [split][d][j] layout -> coalesced across j.
#pragma unroll
    for (int p = 0; p < DP; p++) {
        float a, b;
        unpack2(acc[p], a, b);
        g_part_acc[split][2 * p][j]     = a;
        g_part_acc[split][2 * p + 1][j] = b;
    }
    g_part_deg[split][j] = deg;
}

__global__ void ms_reduce(const float* __restrict__ X, float* __restrict__ Xout) {
    const int j = blockIdx.x * blockDim.x + threadIdx.x;
    if (j >= NPTS) return;

    float deg = 0.0f;
#pragma unroll
    for (int s = 0; s < ISPLITS; s++) deg += g_part_deg[s][j];
    const float inv = ETA / deg;

#pragma unroll
    for (int d = 0; d < DIM; d++) {
        float a = 0.0f;
#pragma unroll
        for (int s = 0; s < ISPLITS; s++) a += g_part_acc[s][d][j];
        Xout[d * NPTS + j] = a * inv + (1.0f - ETA) * X[d * NPTS + j];
    }
}

__global__ void ms_copy(const float* __restrict__ in, float* __restrict__ out, int n) {
    int i = blockIdx.x * blockDim.x + threadIdx.x;
    if (i < n) out[i] = in[i];
}

extern "C" void kernel_launch(void* const* d_in, const int* in_sizes, int n_in,
                              void* d_out, int out_size) {
    const float* x_in = (const float*)d_in[0];
    float* out = (float*)d_out;
    const int frame = DIM * NPTS;  // 294912 floats per iterate

    // Iterate 0 is the input itself.
    ms_copy<<<(frame + 255) / 256, 256>>>(x_in, out, frame);

    for (int tIter = 0; tIter < 3; tIter++) {
        const float* X  = out + (size_t)tIter * frame;
        float*       Xn = out + (size_t)(tIter + 1) * frame;
        dim3 grid(JTILES, ISPLITS);
        ms_partial<<<grid, TILE_J>>>(X);
        ms_reduce<<<(NPTS + 255) / 256, 256>>>(X, Xn);
    }
}

// round 3
// speedup vs baseline: 4.5192x; 4.5192x over previous
#include <cuda_runtime.h>
#include <cuda_bf16.h>
#include <cstdint>

// Mean-shift as unnormalized attention, warp-level bf16 mma.sync (sm_80+ ISA,
// executes on Blackwell HMMA pipe; tcgen05 unavailable: toolchain lowers via
// compute_103 which rejects arch-accelerated features).
//
//   S = (sX)^T (sX)  with s^2 = 2*log2(e)  =>  P = ex2(S) = exp(2 * x_i.x_j)
//   deg_j = sum_i P[i,j];  O[j,:] = sum_i P[j,i] x_i
//   Xnew = eta*O/deg + (1-eta)X

#define NPTS   9216
#define DIM    32
#define ETA    0.5f
#define SCALE  1.6986436f          // sqrt(2*log2(e))
#define TJ     64                  // queries per CTA (4 warps x m16)
#define TI     128                 // keys per tile
#define KSPLIT 4
#define JT     (NPTS / TJ)         // 144
#define NT     (NPTS / (TI * KSPLIT))  // 18 tiles per split

#define KST 80    // key smem row stride bytes (32 bf16 + pad: ldmatrix conflict-free)
#define VST 272   // v smem row stride bytes (128 bf16 + pad)

__device__ __align__(16) __nv_bfloat16 g_s[NPTS * DIM];  // [i][d], scaled
__device__ __align__(16) __nv_bfloat16 g_v[DIM * NPTS];  // [d][i]
__device__ float g_accum[KSPLIT][DIM][NPTS];
__device__ float g_degp[KSPLIT][NPTS];

// ---------------- helpers (baseline ISA only) ----------------
__device__ __forceinline__ uint32_t smem_u32(const void* p) {
    uint32_t a;
    asm("{ .reg .u64 t; cvta.to.shared.u64 t, %1; cvt.u32.u64 %0, t; }" : "=r"(a) : "l"(p));
    return a;
}
__device__ __forceinline__ void ldsm4(uint32_t* r, uint32_t a) {
    asm volatile("ldmatrix.sync.aligned.m8n8.x4.shared.b16 {%0,%1,%2,%3}, [%4];"
        : "=r"(r[0]), "=r"(r[1]), "=r"(r[2]), "=r"(r[3]) : "r"(a));
}
__device__ __forceinline__ void mma16816(float* c, const uint32_t* a,
                                         uint32_t b0, uint32_t b1) {
    asm volatile("mma.sync.aligned.m16n8k16.row.col.f32.bf16.bf16.f32 "
        "{%0,%1,%2,%3}, {%4,%5,%6,%7}, {%8,%9}, {%0,%1,%2,%3};"
        : "+f"(c[0]), "+f"(c[1]), "+f"(c[2]), "+f"(c[3])
        : "r"(a[0]), "r"(a[1]), "r"(a[2]), "r"(a[3]), "r"(b0), "r"(b1));
}
__device__ __forceinline__ float ex2f(float x) {
    float y;
    asm("ex2.approx.ftz.f32 %0, %1;" : "=f"(y) : "f"(x));
    return y;
}
__device__ __forceinline__ uint32_t cvt_bf16x2(float lo, float hi) {
    uint32_t r;  // d.hi = %1, d.lo = %2
    asm("cvt.rn.bf16x2.f32 %0, %1, %2;" : "=r"(r) : "f"(hi), "f"(lo));
    return r;
}
#define CP16(dst, src) asm volatile("cp.async.cg.shared.global [%0], [%1], 16;" :: "r"(dst), "l"(src) : "memory")
#define CP_COMMIT()    asm volatile("cp.async.commit_group;" ::: "memory")
#define CP_WAIT0()     asm volatile("cp.async.wait_group 0;" ::: "memory")
#define CP_WAIT1()     asm volatile("cp.async.wait_group 1;" ::: "memory")

// Stage one key/value tile (128 keys) via cp.async. 8 x 16B per thread.
__device__ __forceinline__ void stage_tiles(uint32_t kdst, uint32_t vdst,
                                            int i0, int tid) {
    const char* ks = reinterpret_cast<const char*>(g_s) + (size_t)i0 * (DIM * 2);
#pragma unroll
    for (int v = 0; v < 4; v++) {
        int idx = v * 128 + tid, row = idx >> 2, c = idx & 3;
        CP16(kdst + row * KST + c * 16, ks + row * 64 + c * 16);
    }
    const char* vs = reinterpret_cast<const char*>(g_v) + (size_t)i0 * 2;
#pragma unroll
    for (int v = 0; v < 4; v++) {
        int idx = v * 128 + tid, row = idx >> 4, c = idx & 15;
        CP16(vdst + row * VST + c * 16, vs + (size_t)row * (NPTS * 2) + c * 16);
    }
}

__global__ void __launch_bounds__(128) ms_attn() {
    __shared__ __align__(16) uint8_t ksm[2][TI * KST];   // 2 x 10240
    __shared__ __align__(16) uint8_t vsm[2][DIM * VST];  // 2 x 8704

    const int tid = threadIdx.x, w = tid >> 5, lane = tid & 31;
    const int jt = blockIdx.x, split = blockIdx.y;
    const int j0 = jt * TJ;
    const int g = lane >> 2, cc = (lane & 3) * 2;

    // ---- stage Q tile (64 rows x 32 bf16) into ksm[0]; build A fragments ----
    {
        const uint4* src = reinterpret_cast<const uint4*>(g_s) + j0 * 4;
#pragma unroll
        for (int v = 0; v < 2; v++) {
            int idx = v * 128 + tid, row = idx >> 2, c = idx & 3;
            *reinterpret_cast<uint4*>(&ksm[0][row * KST + c * 16]) = src[row * 4 + c];
        }
    }
    __syncthreads();
    uint32_t qa[8];
    {
        int m = lane >> 3, r = lane & 7;
        uint32_t base = smem_u32(&ksm[0][(w * 16 + (m & 1) * 8 + r) * KST + (m >> 1) * 16]);
        ldsm4(qa, base);          // k = d 0..15
        ldsm4(qa + 4, base + 32); // k = d 16..31
    }
    __syncthreads();

    float O[16];
#pragma unroll
    for (int i = 0; i < 16; i++) O[i] = 0.0f;
    float dg0 = 0.0f, dg1 = 0.0f;

    const int i00 = split * (NPTS / KSPLIT);

    stage_tiles(smem_u32(&ksm[0][0]), smem_u32(&vsm[0][0]), i00, tid);
    CP_COMMIT();

    for (int it = 0; it < NT; it++) {
        const int buf = it & 1;
        if (it + 1 < NT) {
            stage_tiles(smem_u32(&ksm[buf ^ 1][0]), smem_u32(&vsm[buf ^ 1][0]),
                        i00 + (it + 1) * TI, tid);
            CP_COMMIT();
            CP_WAIT1();
        } else {
            CP_WAIT0();
        }
        __syncthreads();

        // ---- GEMM1: S[16 x 128] = Q x K^T ----
        float s[64];
#pragma unroll
        for (int x = 0; x < 64; x++) s[x] = 0.0f;
#pragma unroll
        for (int ti = 0; ti < 16; ti++) {
            uint32_t kb[4];
            ldsm4(kb, smem_u32(&ksm[buf][(ti * 8 + (lane & 7)) * KST + (lane >> 3) * 16]));
            mma16816(&s[ti * 4], qa, kb[0], kb[1]);
            mma16816(&s[ti * 4], qa + 4, kb[2], kb[3]);
        }

        // ---- P = ex2(S), deg row sums ----
#pragma unroll
        for (int x = 0; x < 64; x++) s[x] = ex2f(s[x]);
#pragma unroll
        for (int ti = 0; ti < 16; ti++) {
            dg0 += s[4 * ti + 0] + s[4 * ti + 1];
            dg1 += s[4 * ti + 2] + s[4 * ti + 3];
        }

        // ---- P fragments (accumulator layout == A-fragment layout) ----
        uint32_t pf[32];
#pragma unroll
        for (int kc = 0; kc < 8; kc++) {
            pf[4 * kc + 0] = cvt_bf16x2(s[8 * kc + 0], s[8 * kc + 1]);
            pf[4 * kc + 1] = cvt_bf16x2(s[8 * kc + 2], s[8 * kc + 3]);
            pf[4 * kc + 2] = cvt_bf16x2(s[8 * kc + 4], s[8 * kc + 5]);
            pf[4 * kc + 3] = cvt_bf16x2(s[8 * kc + 6], s[8 * kc + 7]);
        }

        // ---- GEMM2: O[16 x 32] += P x V ----
#pragma unroll
        for (int dt = 0; dt < 4; dt++) {
#pragma unroll
            for (int q = 0; q < 4; q++) {
                uint32_t vb[4];
                ldsm4(vb, smem_u32(&vsm[buf][(dt * 8 + (lane & 7)) * VST +
                                             (q * 32 + (lane >> 3) * 8) * 2]));
                mma16816(&O[dt * 4], &pf[4 * (2 * q + 0)], vb[0], vb[1]);
                mma16816(&O[dt * 4], &pf[4 * (2 * q + 1)], vb[2], vb[3]);
            }
        }
        __syncthreads();
    }

    // ---- write partials ----
    const int j = j0 + w * 16 + g;
#pragma unroll
    for (int dt = 0; dt < 4; dt++) {
        int d0 = dt * 8 + cc;
        g_accum[split][d0][j]         = O[dt * 4 + 0];
        g_accum[split][d0 + 1][j]     = O[dt * 4 + 1];
        g_accum[split][d0][j + 8]     = O[dt * 4 + 2];
        g_accum[split][d0 + 1][j + 8] = O[dt * 4 + 3];
    }
    dg0 += __shfl_xor_sync(0xFFFFFFFFu, dg0, 1);
    dg0 += __shfl_xor_sync(0xFFFFFFFFu, dg0, 2);
    dg1 += __shfl_xor_sync(0xFFFFFFFFu, dg1, 1);
    dg1 += __shfl_xor_sync(0xFFFFFFFFu, dg1, 2);
    if ((lane & 3) == 0) {
        g_degp[split][j]     = dg0;
        g_degp[split][j + 8] = dg1;
    }
}

// init: copy frame 0 and build bf16 operands
__global__ void ms_init(const float* __restrict__ X, float* __restrict__ out) {
    const int j = blockIdx.x * blockDim.x + threadIdx.x;
    if (j >= NPTS) return;
    uint32_t pk[16];
#pragma unroll
    for (int d = 0; d < DIM; d += 2) {
        float x0 = X[d * NPTS + j];
        float x1 = X[(d + 1) * NPTS + j];
        out[d * NPTS + j] = x0;
        out[(d + 1) * NPTS + j] = x1;
        g_v[d * NPTS + j] = __float2bfloat16(x0);
        g_v[(d + 1) * NPTS + j] = __float2bfloat16(x1);
        pk[d / 2] = cvt_bf16x2(x0 * SCALE, x1 * SCALE);
    }
    uint4* dst = reinterpret_cast<uint4*>(g_s) + j * 4;
#pragma unroll
    for (int q = 0; q < 4; q++)
        dst[q] = make_uint4(pk[4 * q], pk[4 * q + 1], pk[4 * q + 2], pk[4 * q + 3]);
}

// reduce splits, normalize, write next iterate + bf16 operands for next iter
__global__ void ms_reduce(const float* __restrict__ X, float* __restrict__ Xout) {
    const int j = blockIdx.x * blockDim.x + threadIdx.x;
    if (j >= NPTS) return;
    float deg = 0.0f;
#pragma unroll
    for (int sp = 0; sp < KSPLIT; sp++) deg += g_degp[sp][j];
    const float inv = ETA / deg;

    uint32_t pk[16];
#pragma unroll
    for (int d = 0; d < DIM; d += 2) {
        float a0 = 0.0f, a1 = 0.0f;
#pragma unroll
        for (int sp = 0; sp < KSPLIT; sp++) {
            a0 += g_accum[sp][d][j];
            a1 += g_accum[sp][d + 1][j];
        }
        float x0 = a0 * inv + (1.0f - ETA) * X[d * NPTS + j];
        float x1 = a1 * inv + (1.0f - ETA) * X[(d + 1) * NPTS + j];
        Xout[d * NPTS + j] = x0;
        Xout[(d + 1) * NPTS + j] = x1;
        g_v[d * NPTS + j] = __float2bfloat16(x0);
        g_v[(d + 1) * NPTS + j] = __float2bfloat16(x1);
        pk[d / 2] = cvt_bf16x2(x0 * SCALE, x1 * SCALE);
    }
    uint4* dst = reinterpret_cast<uint4*>(g_s) + j * 4;
#pragma unroll
    for (int q = 0; q < 4; q++)
        dst[q] = make_uint4(pk[4 * q], pk[4 * q + 1], pk[4 * q + 2], pk[4 * q + 3]);
}

extern "C" void kernel_launch(void* const* d_in, const int* in_sizes, int n_in,
                              void* d_out, int out_size) {
    const float* x_in = (const float*)d_in[0];
    float* out = (float*)d_out;
    const int frame = DIM * NPTS;

    ms_init<<<(NPTS + 255) / 256, 256>>>(x_in, out);

    for (int tIter = 0; tIter < 3; tIter++) {
        const float* X  = out + (size_t)tIter * frame;
        float*       Xn = out + (size_t)(tIter + 1) * frame;
        dim3 grid(JT, KSPLIT);
        ms_attn<<<grid, 128>>>();
        ms_reduce<<<(NPTS + 255) / 256, 256>>>(X, Xn);
    }
}

// round 4
// speedup vs baseline: 6.0421x; 1.3370x over previous
#include <cuda_runtime.h>
#include <cuda_bf16.h>
#include <cstdint>

// Mean-shift as unnormalized attention, single persistent kernel.
//   S = (sX)^T (sX), s^2 = 2*log2(e)  =>  P = ex2(S) = exp(2*x_i.x_j)
//   deg_j = sum_i P[i,j];  O[j,:] = sum_i P[j,i] x_i
//   Xnew = eta*O/deg + (1-eta)X
// 3 iterations fused via software grid barrier (576 CTAs, all resident:
// 148 SMs x 4 CTAs = 592 capacity; regs<=128 via launch_bounds, smem 19.5KB).

#define NPTS   9216
#define DIM    32
#define ETA    0.5f
#define SCALE  1.6986436f          // sqrt(2*log2(e))
#define TJ     64
#define TI     64
#define KSPLIT 4
#define JT     (NPTS / TJ)             // 144
#define NT     (NPTS / (TI * KSPLIT))  // 36 tiles per split
#define GRID   (JT * KSPLIT)           // 576
#define FRAME  (DIM * NPTS)

#define KST 80    // key row stride bytes (32 bf16 + pad, ldmatrix conflict-free)
#define VST 144   // v row stride bytes (64 bf16 + pad)

__device__ __align__(16) __nv_bfloat16 g_s[NPTS * DIM];  // [i][d], scaled
__device__ __align__(16) __nv_bfloat16 g_v[DIM * NPTS];  // [d][i]
__device__ float g_accum[KSPLIT][DIM][NPTS];
__device__ float g_degp[KSPLIT][NPTS];
__device__ unsigned g_bar;   // monotonic barrier counter (reset at kernel end)
__device__ unsigned g_fin;   // final handshake counter

// ---------------- helpers ----------------
__device__ __forceinline__ uint32_t smem_u32(const void* p) {
    uint32_t a;
    asm("{ .reg .u64 t; cvta.to.shared.u64 t, %1; cvt.u32.u64 %0, t; }" : "=r"(a) : "l"(p));
    return a;
}
__device__ __forceinline__ void ldsm4(uint32_t* r, uint32_t a) {
    asm volatile("ldmatrix.sync.aligned.m8n8.x4.shared.b16 {%0,%1,%2,%3}, [%4];"
        : "=r"(r[0]), "=r"(r[1]), "=r"(r[2]), "=r"(r[3]) : "r"(a));
}
__device__ __forceinline__ void mma16816(float* c, const uint32_t* a,
                                         uint32_t b0, uint32_t b1) {
    asm volatile("mma.sync.aligned.m16n8k16.row.col.f32.bf16.bf16.f32 "
        "{%0,%1,%2,%3}, {%4,%5,%6,%7}, {%8,%9}, {%0,%1,%2,%3};"
        : "+f"(c[0]), "+f"(c[1]), "+f"(c[2]), "+f"(c[3])
        : "r"(a[0]), "r"(a[1]), "r"(a[2]), "r"(a[3]), "r"(b0), "r"(b1));
}
__device__ __forceinline__ float ex2f(float x) {
    float y;
    asm("ex2.approx.ftz.f32 %0, %1;" : "=f"(y) : "f"(x));
    return y;
}
__device__ __forceinline__ uint32_t cvt_bf16x2(float lo, float hi) {
    uint32_t r;
    asm("cvt.rn.bf16x2.f32 %0, %1, %2;" : "=r"(r) : "f"(hi), "f"(lo));
    return r;
}
#define CP16(dst, src) asm volatile("cp.async.cg.shared.global [%0], [%1], 16;" :: "r"(dst), "l"(src) : "memory")
#define CP_COMMIT()    asm volatile("cp.async.commit_group;" ::: "memory")
#define CP_WAIT0()     asm volatile("cp.async.wait_group 0;" ::: "memory")
#define CP_WAIT1()     asm volatile("cp.async.wait_group 1;" ::: "memory")

__device__ __forceinline__ void grid_bar(unsigned tgt) {
    __syncthreads();
    __threadfence();
    if (threadIdx.x == 0) {
        atomicAdd(&g_bar, 1u);
        while (*(volatile unsigned*)&g_bar < tgt) __nanosleep(32);
    }
    __syncthreads();
}

// Stage one 64-key K/V tile via cp.async (L2-only: .cg bypasses stale L1).
__device__ __forceinline__ void stage_tiles(uint32_t kdst, uint32_t vdst,
                                            int i0, int tid) {
    const char* ks = reinterpret_cast<const char*>(g_s) + (size_t)i0 * (DIM * 2);
#pragma unroll
    for (int v = 0; v < 2; v++) {
        int idx = v * 128 + tid, row = idx >> 2, c = idx & 3;
        CP16(kdst + row * KST + c * 16, ks + row * 64 + c * 16);
    }
    const char* vs = reinterpret_cast<const char*>(g_v) + (size_t)i0 * 2;
#pragma unroll
    for (int v = 0; v < 2; v++) {
        int idx = v * 128 + tid, row = idx >> 3, c = idx & 7;
        CP16(vdst + row * VST + c * 16, vs + (size_t)row * (NPTS * 2) + c * 16);
    }
}

__global__ void __launch_bounds__(128, 4)
ms_persist(const float* __restrict__ x_in, float* __restrict__ out) {
    __shared__ __align__(16) uint8_t ksm[2][TI * KST];   // 2 x 5120
    __shared__ __align__(16) uint8_t vsm[2][DIM * VST];  // 2 x 4608

    const int tid = threadIdx.x, w = tid >> 5, lane = tid & 31;
    const int jt = blockIdx.x, split = blockIdx.y;
    const unsigned gid = (blockIdx.y * JT + blockIdx.x) * 128u + tid;
    unsigned tgt = 0;

    // ---------------- phase 0: init (4 threads per pixel) ----------------
    if (gid < NPTS * 4u) {
        const int j = gid >> 2, d0 = (gid & 3) * 8;
        uint32_t pk[4];
#pragma unroll
        for (int q = 0; q < 4; q++) {
            int d = d0 + q * 2;
            float x0 = x_in[d * NPTS + j];
            float x1 = x_in[(d + 1) * NPTS + j];
            out[d * NPTS + j] = x0;
            out[(d + 1) * NPTS + j] = x1;
            g_v[d * NPTS + j] = __float2bfloat16(x0);
            g_v[(d + 1) * NPTS + j] = __float2bfloat16(x1);
            pk[q] = cvt_bf16x2(x0 * SCALE, x1 * SCALE);
        }
        *reinterpret_cast<uint4*>(g_s + j * DIM + d0) =
            make_uint4(pk[0], pk[1], pk[2], pk[3]);
    }
    tgt += GRID; grid_bar(tgt);

    for (int t = 0; t < 3; t++) {
        // ---------------- attention phase ----------------
        const int j0 = jt * TJ;
        // stage Q (64 x 32 bf16) into ksm[0]; ldcg avoids stale L1
        {
            const uint4* src = reinterpret_cast<const uint4*>(g_s) + j0 * 4;
#pragma unroll
            for (int v = 0; v < 2; v++) {
                int idx = v * 128 + tid, row = idx >> 2, c = idx & 3;
                uint4 val = __ldcg(&src[row * 4 + c]);
                *reinterpret_cast<uint4*>(&ksm[0][row * KST + c * 16]) = val;
            }
        }
        __syncthreads();
        uint32_t qa[8];
        {
            int m = lane >> 3, r = lane & 7;
            uint32_t base = smem_u32(&ksm[0][(w * 16 + (m & 1) * 8 + r) * KST + (m >> 1) * 16]);
            ldsm4(qa, base);
            ldsm4(qa + 4, base + 32);
        }
        __syncthreads();

        float O[16];
#pragma unroll
        for (int i = 0; i < 16; i++) O[i] = 0.0f;
        float dg0 = 0.0f, dg1 = 0.0f;

        const int i00 = split * (NPTS / KSPLIT);
        stage_tiles(smem_u32(&ksm[0][0]), smem_u32(&vsm[0][0]), i00, tid);
        CP_COMMIT();

        for (int it = 0; it < NT; it++) {
            const int buf = it & 1;
            if (it + 1 < NT) {
                stage_tiles(smem_u32(&ksm[buf ^ 1][0]), smem_u32(&vsm[buf ^ 1][0]),
                            i00 + (it + 1) * TI, tid);
                CP_COMMIT();
                CP_WAIT1();
            } else {
                CP_WAIT0();
            }
            __syncthreads();

            // GEMM1: S[16 x 64] = Q x K^T
            float s[32];
#pragma unroll
            for (int x = 0; x < 32; x++) s[x] = 0.0f;
#pragma unroll
            for (int ti = 0; ti < 8; ti++) {
                uint32_t kb[4];
                ldsm4(kb, smem_u32(&ksm[buf][(ti * 8 + (lane & 7)) * KST + (lane >> 3) * 16]));
                mma16816(&s[ti * 4], qa, kb[0], kb[1]);
                mma16816(&s[ti * 4], qa + 4, kb[2], kb[3]);
            }

            // P = ex2(S); deg row sums
#pragma unroll
            for (int x = 0; x < 32; x++) s[x] = ex2f(s[x]);
#pragma unroll
            for (int ti = 0; ti < 8; ti++) {
                dg0 += s[4 * ti + 0] + s[4 * ti + 1];
                dg1 += s[4 * ti + 2] + s[4 * ti + 3];
            }

            // P fragments (accumulator layout == A-fragment layout)
            uint32_t pf[16];
#pragma unroll
            for (int kc = 0; kc < 4; kc++) {
                pf[4 * kc + 0] = cvt_bf16x2(s[8 * kc + 0], s[8 * kc + 1]);
                pf[4 * kc + 1] = cvt_bf16x2(s[8 * kc + 2], s[8 * kc + 3]);
                pf[4 * kc + 2] = cvt_bf16x2(s[8 * kc + 4], s[8 * kc + 5]);
                pf[4 * kc + 3] = cvt_bf16x2(s[8 * kc + 6], s[8 * kc + 7]);
            }

            // GEMM2: O[16 x 32] += P x V
#pragma unroll
            for (int dt = 0; dt < 4; dt++) {
#pragma unroll
                for (int q = 0; q < 2; q++) {
                    uint32_t vb[4];
                    ldsm4(vb, smem_u32(&vsm[buf][(dt * 8 + (lane & 7)) * VST +
                                                 (q * 32 + (lane >> 3) * 8) * 2]));
                    mma16816(&O[dt * 4], &pf[4 * (2 * q + 0)], vb[0], vb[1]);
                    mma16816(&O[dt * 4], &pf[4 * (2 * q + 1)], vb[2], vb[3]);
                }
            }
            __syncthreads();
        }

        // write partials
        {
            const int j = j0 + w * 16 + (lane >> 2);
            const int cc = (lane & 3) * 2;
#pragma unroll
            for (int dt = 0; dt < 4; dt++) {
                int d0 = dt * 8 + cc;
                g_accum[split][d0][j]         = O[dt * 4 + 0];
                g_accum[split][d0 + 1][j]     = O[dt * 4 + 1];
                g_accum[split][d0][j + 8]     = O[dt * 4 + 2];
                g_accum[split][d0 + 1][j + 8] = O[dt * 4 + 3];
            }
            float a0 = dg0, a1 = dg1;
            a0 += __shfl_xor_sync(0xFFFFFFFFu, a0, 1);
            a0 += __shfl_xor_sync(0xFFFFFFFFu, a0, 2);
            a1 += __shfl_xor_sync(0xFFFFFFFFu, a1, 1);
            a1 += __shfl_xor_sync(0xFFFFFFFFu, a1, 2);
            if ((lane & 3) == 0) {
                g_degp[split][j]     = a0;
                g_degp[split][j + 8] = a1;
            }
        }
        tgt += GRID; grid_bar(tgt);

        // ---------------- reduce phase (4 threads per pixel) ----------------
        if (gid < NPTS * 4u) {
            const int j = gid >> 2, d0 = (gid & 3) * 8;
            float deg = 0.0f;
#pragma unroll
            for (int sp = 0; sp < KSPLIT; sp++) deg += __ldcg(&g_degp[sp][j]);
            const float inv = ETA / deg;
            const float* X  = out + (size_t)t * FRAME;
            float*       Xn = out + (size_t)(t + 1) * FRAME;
            uint32_t pk[4];
#pragma unroll
            for (int q = 0; q < 4; q++) {
                int d = d0 + q * 2;
                float a0 = 0.0f, a1 = 0.0f;
#pragma unroll
                for (int sp = 0; sp < KSPLIT; sp++) {
                    a0 += __ldcg(&g_accum[sp][d][j]);
                    a1 += __ldcg(&g_accum[sp][d + 1][j]);
                }
                float x0 = a0 * inv + (1.0f - ETA) * X[d * NPTS + j];
                float x1 = a1 * inv + (1.0f - ETA) * X[(d + 1) * NPTS + j];
                Xn[d * NPTS + j] = x0;
                Xn[(d + 1) * NPTS + j] = x1;
                if (t < 2) {
                    g_v[d * NPTS + j] = __float2bfloat16(x0);
                    g_v[(d + 1) * NPTS + j] = __float2bfloat16(x1);
                    pk[q] = cvt_bf16x2(x0 * SCALE, x1 * SCALE);
                }
            }
            if (t < 2)
                *reinterpret_cast<uint4*>(g_s + j * DIM + d0) =
                    make_uint4(pk[0], pk[1], pk[2], pk[3]);
        }
        if (t < 2) { tgt += GRID; grid_bar(tgt); }
    }

    // ---------------- epilogue: counter reset handshake ----------------
    __syncthreads();
    __threadfence();
    if (tid == 0) atomicAdd(&g_fin, 1u);
    if (gid == 0) {
        while (*(volatile unsigned*)&g_fin < GRID) __nanosleep(64);
        *(volatile unsigned*)&g_bar = 0;
        *(volatile unsigned*)&g_fin = 0;
        __threadfence();
    }
}

extern "C" void kernel_launch(void* const* d_in, const int* in_sizes, int n_in,
                              void* d_out, int out_size) {
    const float* x_in = (const float*)d_in[0];
    float* out = (float*)d_out;
    dim3 grid(JT, KSPLIT);
    ms_persist<<<grid, 128>>>(x_in, out);
}

// round 5
// speedup vs baseline: 6.1217x; 1.0132x over previous
#include <cuda_runtime.h>
#include <cuda_fp16.h>
#include <cstdint>

// Mean-shift as unnormalized attention, single persistent kernel (f16 path).
//   S = (sX)^T (sX), s^2 = 2*log2(e)  =>  P = ex2(S) = exp(2*x_i.x_j)
//   deg = P @ ones (extra tensor-core mma, fp32 accum)
//   O = P @ V;  Xnew = eta*O/deg + (1-eta)X
// 3 iterations fused via software grid barrier (576 CTAs all resident).

#define NPTS   9216
#define DIM    32
#define ETA    0.5f
#define SCALE  1.6986436f          // sqrt(2*log2(e))
#define TJ     64
#define TI     64
#define KSPLIT 4
#define JT     (NPTS / TJ)             // 144
#define NT     (NPTS / (TI * KSPLIT))  // 36 tiles per split
#define GRID   (JT * KSPLIT)           // 576
#define FRAME  (DIM * NPTS)

#define KST 80    // key row stride bytes (32 f16 + pad, ldmatrix conflict-free)
#define VST 144   // v row stride bytes (64 f16 + pad)
#define ONES2 0x3C003C00u   // f16x2 {1.0, 1.0}

__device__ __align__(16) __half g_s[NPTS * DIM];  // [i][d], scaled, f16
__device__ __align__(16) __half g_v[DIM * NPTS];  // [d][i], f16
__device__ float g_accum[KSPLIT][DIM][NPTS];
__device__ float g_degp[KSPLIT][NPTS];
__device__ unsigned g_bar;
__device__ unsigned g_fin;

// ---------------- helpers ----------------
__device__ __forceinline__ uint32_t smem_u32(const void* p) {
    uint32_t a;
    asm("{ .reg .u64 t; cvta.to.shared.u64 t, %1; cvt.u32.u64 %0, t; }" : "=r"(a) : "l"(p));
    return a;
}
__device__ __forceinline__ void ldsm4(uint32_t* r, uint32_t a) {
    asm volatile("ldmatrix.sync.aligned.m8n8.x4.shared.b16 {%0,%1,%2,%3}, [%4];"
        : "=r"(r[0]), "=r"(r[1]), "=r"(r[2]), "=r"(r[3]) : "r"(a));
}
__device__ __forceinline__ void mma16816(float* c, const uint32_t* a,
                                         uint32_t b0, uint32_t b1) {
    asm volatile("mma.sync.aligned.m16n8k16.row.col.f32.f16.f16.f32 "
        "{%0,%1,%2,%3}, {%4,%5,%6,%7}, {%8,%9}, {%0,%1,%2,%3};"
        : "+f"(c[0]), "+f"(c[1]), "+f"(c[2]), "+f"(c[3])
        : "r"(a[0]), "r"(a[1]), "r"(a[2]), "r"(a[3]), "r"(b0), "r"(b1));
}
__device__ __forceinline__ uint32_t cvt_f16x2(float lo, float hi) {
    uint32_t r;
    asm("cvt.rn.f16x2.f32 %0, %1, %2;" : "=r"(r) : "f"(hi), "f"(lo));
    return r;
}
__device__ __forceinline__ uint32_t ex2_h2(uint32_t x) {
    uint32_t y;
    asm("ex2.approx.f16x2 %0, %1;" : "=r"(y) : "r"(x));
    return y;
}
#define CP16(dst, src) asm volatile("cp.async.cg.shared.global [%0], [%1], 16;" :: "r"(dst), "l"(src) : "memory")
#define CP_COMMIT()    asm volatile("cp.async.commit_group;" ::: "memory")
#define CP_WAIT0()     asm volatile("cp.async.wait_group 0;" ::: "memory")
#define CP_WAIT1()     asm volatile("cp.async.wait_group 1;" ::: "memory")

__device__ __forceinline__ void grid_bar(unsigned tgt) {
    __syncthreads();
    __threadfence();
    if (threadIdx.x == 0) {
        atomicAdd(&g_bar, 1u);
        while (*(volatile unsigned*)&g_bar < tgt) __nanosleep(32);
    }
    __syncthreads();
}

// Stage one 64-key K/V tile via cp.async (.cg: L2-only, avoids stale L1).
__device__ __forceinline__ void stage_tiles(uint32_t kdst, uint32_t vdst,
                                            int i0, int tid) {
    const char* ks = reinterpret_cast<const char*>(g_s) + (size_t)i0 * (DIM * 2);
#pragma unroll
    for (int v = 0; v < 2; v++) {
        int idx = v * 128 + tid, row = idx >> 2, c = idx & 3;
        CP16(kdst + row * KST + c * 16, ks + row * 64 + c * 16);
    }
    const char* vs = reinterpret_cast<const char*>(g_v) + (size_t)i0 * 2;
#pragma unroll
    for (int v = 0; v < 2; v++) {
        int idx = v * 128 + tid, row = idx >> 3, c = idx & 7;
        CP16(vdst + row * VST + c * 16, vs + (size_t)row * (NPTS * 2) + c * 16);
    }
}

__global__ void __launch_bounds__(128, 4)
ms_persist(const float* __restrict__ x_in, float* __restrict__ out) {
    __shared__ __align__(16) uint8_t ksm[2][TI * KST];   // 2 x 5120
    __shared__ __align__(16) uint8_t vsm[2][DIM * VST];  // 2 x 4608

    const int tid = threadIdx.x, w = tid >> 5, lane = tid & 31;
    const int jt = blockIdx.x, split = blockIdx.y;
    const unsigned gid = (blockIdx.y * JT + blockIdx.x) * 128u + tid;
    unsigned tgt = 0;

    // ---------------- phase 0: init (4 threads per pixel) ----------------
    if (gid < NPTS * 4u) {
        const int j = gid >> 2, d0 = (gid & 3) * 8;
        uint32_t pk[4];
#pragma unroll
        for (int q = 0; q < 4; q++) {
            int d = d0 + q * 2;
            float x0 = x_in[d * NPTS + j];
            float x1 = x_in[(d + 1) * NPTS + j];
            out[d * NPTS + j] = x0;
            out[(d + 1) * NPTS + j] = x1;
            g_v[d * NPTS + j] = __float2half(x0);
            g_v[(d + 1) * NPTS + j] = __float2half(x1);
            pk[q] = cvt_f16x2(x0 * SCALE, x1 * SCALE);
        }
        *reinterpret_cast<uint4*>(g_s + j * DIM + d0) =
            make_uint4(pk[0], pk[1], pk[2], pk[3]);
    }
    tgt += GRID; grid_bar(tgt);

    for (int t = 0; t < 3; t++) {
        // ---------------- attention phase ----------------
        const int j0 = jt * TJ;
        {
            const uint4* src = reinterpret_cast<const uint4*>(g_s) + j0 * 4;
#pragma unroll
            for (int v = 0; v < 2; v++) {
                int idx = v * 128 + tid, row = idx >> 2, c = idx & 3;
                uint4 val = __ldcg(&src[row * 4 + c]);
                *reinterpret_cast<uint4*>(&ksm[0][row * KST + c * 16]) = val;
            }
        }
        __syncthreads();
        uint32_t qa[8];
        {
            int m = lane >> 3, r = lane & 7;
            uint32_t base = smem_u32(&ksm[0][(w * 16 + (m & 1) * 8 + r) * KST + (m >> 1) * 16]);
            ldsm4(qa, base);
            ldsm4(qa + 4, base + 32);
        }
        __syncthreads();

        float O[16];
#pragma unroll
        for (int i = 0; i < 16; i++) O[i] = 0.0f;
        float dacc[4] = {0.0f, 0.0f, 0.0f, 0.0f};

        const int i00 = split * (NPTS / KSPLIT);
        stage_tiles(smem_u32(&ksm[0][0]), smem_u32(&vsm[0][0]), i00, tid);
        CP_COMMIT();

        for (int it = 0; it < NT; it++) {
            const int buf = it & 1;
            if (it + 1 < NT) {
                stage_tiles(smem_u32(&ksm[buf ^ 1][0]), smem_u32(&vsm[buf ^ 1][0]),
                            i00 + (it + 1) * TI, tid);
                CP_COMMIT();
                CP_WAIT1();
            } else {
                CP_WAIT0();
            }
            __syncthreads();

            // GEMM1: S[16 x 64] = Q x K^T
            float s[32];
#pragma unroll
            for (int x = 0; x < 32; x++) s[x] = 0.0f;
#pragma unroll
            for (int ti = 0; ti < 8; ti++) {
                uint32_t kb[4];
                ldsm4(kb, smem_u32(&ksm[buf][(ti * 8 + (lane & 7)) * KST + (lane >> 3) * 16]));
                mma16816(&s[ti * 4], qa, kb[0], kb[1]);
                mma16816(&s[ti * 4], qa + 4, kb[2], kb[3]);
            }

            // P = ex2(S) as f16x2 pairs: directly the A-fragment registers.
            uint32_t pf[16];
#pragma unroll
            for (int x = 0; x < 16; x++)
                pf[x] = ex2_h2(cvt_f16x2(s[2 * x], s[2 * x + 1]));

            // deg += P @ ones  (fp32, tensor pipe, deterministic)
#pragma unroll
            for (int kc = 0; kc < 4; kc++)
                mma16816(dacc, &pf[4 * kc], ONES2, ONES2);

            // GEMM2: O[16 x 32] += P x V
#pragma unroll
            for (int dt = 0; dt < 4; dt++) {
#pragma unroll
                for (int q = 0; q < 2; q++) {
                    uint32_t vb[4];
                    ldsm4(vb, smem_u32(&vsm[buf][(dt * 8 + (lane & 7)) * VST +
                                                 (q * 32 + (lane >> 3) * 8) * 2]));
                    mma16816(&O[dt * 4], &pf[4 * (2 * q + 0)], vb[0], vb[1]);
                    mma16816(&O[dt * 4], &pf[4 * (2 * q + 1)], vb[2], vb[3]);
                }
            }
            __syncthreads();
        }

        // write partials (deg: every lane of a quad holds it; one writes)
        {
            const int j = j0 + w * 16 + (lane >> 2);
            const int cc = (lane & 3) * 2;
#pragma unroll
            for (int dt = 0; dt < 4; dt++) {
                int d0 = dt * 8 + cc;
                g_accum[split][d0][j]         = O[dt * 4 + 0];
                g_accum[split][d0 + 1][j]     = O[dt * 4 + 1];
                g_accum[split][d0][j + 8]     = O[dt * 4 + 2];
                g_accum[split][d0 + 1][j + 8] = O[dt * 4 + 3];
            }
            if ((lane & 3) == 0) {
                g_degp[split][j]     = dacc[0];
                g_degp[split][j + 8] = dacc[2];
            }
        }
        tgt += GRID; grid_bar(tgt);

        // ---------------- reduce phase (4 threads per pixel) ----------------
        if (gid < NPTS * 4u) {
            const int j = gid >> 2, d0 = (gid & 3) * 8;
            float deg = 0.0f;
#pragma unroll
            for (int sp = 0; sp < KSPLIT; sp++) deg += __ldcg(&g_degp[sp][j]);
            const float inv = ETA / deg;
            const float* X  = out + (size_t)t * FRAME;
            float*       Xn = out + (size_t)(t + 1) * FRAME;
            uint32_t pk[4];
#pragma unroll
            for (int q = 0; q < 4; q++) {
                int d = d0 + q * 2;
                float a0 = 0.0f, a1 = 0.0f;
#pragma unroll
                for (int sp = 0; sp < KSPLIT; sp++) {
                    a0 += __ldcg(&g_accum[sp][d][j]);
                    a1 += __ldcg(&g_accum[sp][d + 1][j]);
                }
                float x0 = a0 * inv + (1.0f - ETA) * X[d * NPTS + j];
                float x1 = a1 * inv + (1.0f - ETA) * X[(d + 1) * NPTS + j];
                Xn[d * NPTS + j] = x0;
                Xn[(d + 1) * NPTS + j] = x1;
                if (t < 2) {
                    g_v[d * NPTS + j] = __float2half(x0);
                    g_v[(d + 1) * NPTS + j] = __float2half(x1);
                    pk[q] = cvt_f16x2(x0 * SCALE, x1 * SCALE);
                }
            }
            if (t < 2)
                *reinterpret_cast<uint4*>(g_s + j * DIM + d0) =
                    make_uint4(pk[0], pk[1], pk[2], pk[3]);
        }
        if (t < 2) { tgt += GRID; grid_bar(tgt); }
    }

    // ---------------- epilogue: counter reset handshake ----------------
    __syncthreads();
    __threadfence();
    if (tid == 0) atomicAdd(&g_fin, 1u);
    if (gid == 0) {
        while (*(volatile unsigned*)&g_fin < GRID) __nanosleep(64);
        *(volatile unsigned*)&g_bar = 0;
        *(volatile unsigned*)&g_fin = 0;
        __threadfence();
    }
}

extern "C" void kernel_launch(void* const* d_in, const int* in_sizes, int n_in,
                              void* d_out, int out_size) {
    const float* x_in = (const float*)d_in[0];
    float* out = (float*)d_out;
    dim3 grid(JT, KSPLIT);
    ms_persist<<<grid, 128>>>(x_in, out);
}

// round 6
// speedup vs baseline: 6.7653x; 1.1051x over previous
#include <cuda_runtime.h>
#include <cuda_fp16.h>
#include <cstdint>

// Mean-shift as unnormalized attention, single persistent kernel (f16 path).
//   S = (sX)^T (sX), s^2 = 2*log2(e)  =>  P = ex2(S) = exp(2*x_i.x_j)
//   deg = P @ ones (tensor-core mma, fp32 accum)
//   O = P @ V;  Xnew = eta*O/deg + (1-eta)X
// 2x2 warp tiling (query-half x key-half) halves redundant LDSM traffic;
// cross-warp O/deg reduction once per j-tile via smem.

#define NPTS   9216
#define DIM    32
#define ETA    0.5f
#define SCALE  1.6986436f          // sqrt(2*log2(e))
#define TJ     64
#define TI     64
#define KSPLIT 4
#define JT     (NPTS / TJ)             // 144
#define NT     (NPTS / (TI * KSPLIT))  // 36 tiles per split
#define GRID   (JT * KSPLIT)           // 576
#define FRAME  (DIM * NPTS)

#define KST 80      // key row stride bytes (32 f16 + pad)
#define VST 144     // v row stride bytes (64 f16 + pad)
#define ONES2 0x3C003C00u

#define KBUF 5120               // TI * KST
#define VBUF 4608               // DIM * VST
#define SH_K 0                  // 2 x 5120
#define SH_V (2 * KBUF)         // 2 x 4608
#define SH_X 0                  // O exchange (8KB), aliases K staging
#define SH_XD 8192              // deg exchange (1KB)
#define SMEM_BYTES (2 * KBUF + 2 * VBUF)   // 19456

__device__ __align__(16) __half g_s[NPTS * DIM];  // [i][d], scaled, f16
__device__ __align__(16) __half g_v[DIM * NPTS];  // [d][i], f16
__device__ float g_accum[KSPLIT][DIM][NPTS];
__device__ float g_degp[KSPLIT][NPTS];
__device__ unsigned g_bar;
__device__ unsigned g_fin;

// ---------------- helpers ----------------
__device__ __forceinline__ uint32_t smem_u32(const void* p) {
    uint32_t a;
    asm("{ .reg .u64 t; cvta.to.shared.u64 t, %1; cvt.u32.u64 %0, t; }" : "=r"(a) : "l"(p));
    return a;
}
__device__ __forceinline__ void ldsm4(uint32_t* r, uint32_t a) {
    asm volatile("ldmatrix.sync.aligned.m8n8.x4.shared.b16 {%0,%1,%2,%3}, [%4];"
        : "=r"(r[0]), "=r"(r[1]), "=r"(r[2]), "=r"(r[3]) : "r"(a));
}
__device__ __forceinline__ void mma16816(float* c, const uint32_t* a,
                                         uint32_t b0, uint32_t b1) {
    asm volatile("mma.sync.aligned.m16n8k16.row.col.f32.f16.f16.f32 "
        "{%0,%1,%2,%3}, {%4,%5,%6,%7}, {%8,%9}, {%0,%1,%2,%3};"
        : "+f"(c[0]), "+f"(c[1]), "+f"(c[2]), "+f"(c[3])
        : "r"(a[0]), "r"(a[1]), "r"(a[2]), "r"(a[3]), "r"(b0), "r"(b1));
}
__device__ __forceinline__ uint32_t cvt_f16x2(float lo, float hi) {
    uint32_t r;
    asm("cvt.rn.f16x2.f32 %0, %1, %2;" : "=r"(r) : "f"(hi), "f"(lo));
    return r;
}
__device__ __forceinline__ uint32_t ex2_h2(uint32_t x) {
    uint32_t y;
    asm("ex2.approx.f16x2 %0, %1;" : "=r"(y) : "r"(x));
    return y;
}
#define CP16(dst, src) asm volatile("cp.async.cg.shared.global [%0], [%1], 16;" :: "r"(dst), "l"(src) : "memory")
#define CP_COMMIT()    asm volatile("cp.async.commit_group;" ::: "memory")
#define CP_WAIT0()     asm volatile("cp.async.wait_group 0;" ::: "memory")
#define CP_WAIT1()     asm volatile("cp.async.wait_group 1;" ::: "memory")

__device__ __forceinline__ void grid_bar(unsigned tgt) {
    __syncthreads();
    __threadfence();
    if (threadIdx.x == 0) {
        atomicAdd(&g_bar, 1u);
        while (*(volatile unsigned*)&g_bar < tgt) __nanosleep(32);
    }
    __syncthreads();
}

// Stage one 64-key K/V tile via cp.async (.cg: L2-only, avoids stale L1).
__device__ __forceinline__ void stage_tiles(uint32_t kdst, uint32_t vdst,
                                            int i0, int tid) {
    const char* ks = reinterpret_cast<const char*>(g_s) + (size_t)i0 * (DIM * 2);
#pragma unroll
    for (int v = 0; v < 2; v++) {
        int idx = v * 128 + tid, row = idx >> 2, c = idx & 3;
        CP16(kdst + row * KST + c * 16, ks + row * 64 + c * 16);
    }
    const char* vs = reinterpret_cast<const char*>(g_v) + (size_t)i0 * 2;
#pragma unroll
    for (int v = 0; v < 2; v++) {
        int idx = v * 128 + tid, row = idx >> 3, c = idx & 7;
        CP16(vdst + row * VST + c * 16, vs + (size_t)row * (NPTS * 2) + c * 16);
    }
}

__global__ void __launch_bounds__(128, 4)
ms_persist(const float* __restrict__ x_in, float* __restrict__ out) {
    __shared__ __align__(16) uint8_t sm[SMEM_BYTES];

    const int tid = threadIdx.x, w = tid >> 5, lane = tid & 31;
    const int wq = w >> 1, wk = w & 1;
    const int jt = blockIdx.x, split = blockIdx.y;
    const unsigned gid = (blockIdx.y * JT + blockIdx.x) * 128u + tid;
    const uint32_t smbase = smem_u32(sm);
    unsigned tgt = 0;

    // ---------------- phase 0: init (4 threads per pixel) ----------------
    if (gid < NPTS * 4u) {
        const int j = gid >> 2, d0 = (gid & 3) * 8;
        uint32_t pk[4];
#pragma unroll
        for (int q = 0; q < 4; q++) {
            int d = d0 + q * 2;
            float x0 = x_in[d * NPTS + j];
            float x1 = x_in[(d + 1) * NPTS + j];
            out[d * NPTS + j] = x0;
            out[(d + 1) * NPTS + j] = x1;
            g_v[d * NPTS + j] = __float2half(x0);
            g_v[(d + 1) * NPTS + j] = __float2half(x1);
            pk[q] = cvt_f16x2(x0 * SCALE, x1 * SCALE);
        }
        *reinterpret_cast<uint4*>(g_s + j * DIM + d0) =
            make_uint4(pk[0], pk[1], pk[2], pk[3]);
    }
    tgt += GRID; grid_bar(tgt);

    // hoisted ldsm addresses (buf 0; add KBUF/VBUF for buf 1)
    uint32_t ka0[4], va0[4];
#pragma unroll
    for (int nt = 0; nt < 4; nt++)
        ka0[nt] = smbase + SH_K + (wk * 32 + nt * 8 + (lane & 7)) * KST + (lane >> 3) * 16;
#pragma unroll
    for (int dt = 0; dt < 4; dt++)
        va0[dt] = smbase + SH_V + (dt * 8 + (lane & 7)) * VST + (wk * 32 + (lane >> 3) * 8) * 2;

    for (int t = 0; t < 3; t++) {
        // ---------------- attention phase ----------------
        const int j0 = jt * TJ;
        {
            const uint4* src = reinterpret_cast<const uint4*>(g_s) + j0 * 4;
#pragma unroll
            for (int v = 0; v < 2; v++) {
                int idx = v * 128 + tid, row = idx >> 2, c = idx & 3;
                uint4 val = __ldcg(&src[row * 4 + c]);
                *reinterpret_cast<uint4*>(&sm[SH_K + row * KST + c * 16]) = val;
            }
        }
        __syncthreads();
        // Q A-fragments: 2 mtiles (rows wq*32 + mt*16), k = 0..31
        uint32_t qa[16];
        {
            int m = lane >> 3, r = lane & 7;
#pragma unroll
            for (int mt = 0; mt < 2; mt++) {
                uint32_t base = smbase + SH_K +
                    (wq * 32 + mt * 16 + (m & 1) * 8 + r) * KST + (m >> 1) * 16;
                ldsm4(qa + mt * 8, base);
                ldsm4(qa + mt * 8 + 4, base + 32);
            }
        }
        __syncthreads();

        float O[32];
#pragma unroll
        for (int i = 0; i < 32; i++) O[i] = 0.0f;
        float dacc[8];
#pragma unroll
        for (int i = 0; i < 8; i++) dacc[i] = 0.0f;

        const int i00 = split * (NPTS / KSPLIT);
        stage_tiles(smbase + SH_K, smbase + SH_V, i00, tid);
        CP_COMMIT();

        for (int it = 0; it < NT; it++) {
            const int buf = it & 1;
            if (it + 1 < NT) {
                stage_tiles(smbase + SH_K + (buf ^ 1) * KBUF,
                            smbase + SH_V + (buf ^ 1) * VBUF,
                            i00 + (it + 1) * TI, tid);
                CP_COMMIT();
                CP_WAIT1();
            } else {
                CP_WAIT0();
            }
            __syncthreads();
            const uint32_t kofs = buf * KBUF, vofs = buf * VBUF;

            // GEMM1: S[2 x 16 rows][32 keys] = Q x K^T
            float s[32];
#pragma unroll
            for (int x = 0; x < 32; x++) s[x] = 0.0f;
#pragma unroll
            for (int nt = 0; nt < 4; nt++) {
                uint32_t kb[4];
                ldsm4(kb, ka0[nt] + kofs);
                mma16816(&s[nt * 4],      qa,      kb[0], kb[1]);
                mma16816(&s[nt * 4],      qa + 4,  kb[2], kb[3]);
                mma16816(&s[16 + nt * 4], qa + 8,  kb[0], kb[1]);
                mma16816(&s[16 + nt * 4], qa + 12, kb[2], kb[3]);
            }

            // P = ex2(S) as f16x2 pairs -> A-fragments for GEMM2
            uint32_t pf[16];
#pragma unroll
            for (int mt = 0; mt < 2; mt++) {
#pragma unroll
                for (int kh = 0; kh < 2; kh++) {
                    const float* sa = &s[mt * 16 + kh * 8];
                    uint32_t* pa = &pf[mt * 8 + kh * 4];
                    pa[0] = ex2_h2(cvt_f16x2(sa[0], sa[1]));
                    pa[1] = ex2_h2(cvt_f16x2(sa[2], sa[3]));
                    pa[2] = ex2_h2(cvt_f16x2(sa[4], sa[5]));
                    pa[3] = ex2_h2(cvt_f16x2(sa[6], sa[7]));
                }
            }

            // deg += P @ ones (fp32, tensor pipe)
#pragma unroll
            for (int mt = 0; mt < 2; mt++) {
                mma16816(&dacc[mt * 4], &pf[mt * 8],     ONES2, ONES2);
                mma16816(&dacc[mt * 4], &pf[mt * 8 + 4], ONES2, ONES2);
            }

            // GEMM2: O[2 x 16 rows][32 d] += P x V  (V shared across mtiles)
#pragma unroll
            for (int dt = 0; dt < 4; dt++) {
                uint32_t vb[4];
                ldsm4(vb, va0[dt] + vofs);
                mma16816(&O[dt * 4],      &pf[0],  vb[0], vb[1]);
                mma16816(&O[dt * 4],      &pf[4],  vb[2], vb[3]);
                mma16816(&O[16 + dt * 4], &pf[8],  vb[0], vb[1]);
                mma16816(&O[16 + dt * 4], &pf[12], vb[2], vb[3]);
            }
            __syncthreads();
        }

        // ---- cross-warp (wk) reduction of O and deg via smem ----
        if (wk == 1) {
#pragma unroll
            for (int r4 = 0; r4 < 8; r4++)
                *reinterpret_cast<float4*>(&sm[SH_X + wq * 4096 + r4 * 512 + lane * 16]) =
                    make_float4(O[r4 * 4], O[r4 * 4 + 1], O[r4 * 4 + 2], O[r4 * 4 + 3]);
            *reinterpret_cast<float2*>(&sm[SH_XD + wq * 512 + lane * 8]) =
                make_float2(dacc[0], dacc[2]);
            *reinterpret_cast<float2*>(&sm[SH_XD + wq * 512 + 256 + lane * 8]) =
                make_float2(dacc[4], dacc[6]);
        }
        __syncthreads();
        if (wk == 0) {
#pragma unroll
            for (int r4 = 0; r4 < 8; r4++) {
                float4 pv = *reinterpret_cast<const float4*>(
                    &sm[SH_X + wq * 4096 + r4 * 512 + lane * 16]);
                O[r4 * 4]     += pv.x;
                O[r4 * 4 + 1] += pv.y;
                O[r4 * 4 + 2] += pv.z;
                O[r4 * 4 + 3] += pv.w;
            }
            float2 p0 = *reinterpret_cast<const float2*>(&sm[SH_XD + wq * 512 + lane * 8]);
            float2 p1 = *reinterpret_cast<const float2*>(&sm[SH_XD + wq * 512 + 256 + lane * 8]);
            dacc[0] += p0.x; dacc[2] += p0.y;
            dacc[4] += p1.x; dacc[6] += p1.y;

#pragma unroll
            for (int mt = 0; mt < 2; mt++) {
                const int jj = j0 + wq * 32 + mt * 16 + (lane >> 2);
#pragma unroll
                for (int dt = 0; dt < 4; dt++) {
                    int d0 = dt * 8 + 2 * (lane & 3);
                    g_accum[split][d0][jj]         = O[mt * 16 + dt * 4 + 0];
                    g_accum[split][d0 + 1][jj]     = O[mt * 16 + dt * 4 + 1];
                    g_accum[split][d0][jj + 8]     = O[mt * 16 + dt * 4 + 2];
                    g_accum[split][d0 + 1][jj + 8] = O[mt * 16 + dt * 4 + 3];
                }
                if ((lane & 3) == 0) {
                    g_degp[split][jj]     = dacc[mt * 4 + 0];
                    g_degp[split][jj + 8] = dacc[mt * 4 + 2];
                }
            }
        }
        tgt += GRID; grid_bar(tgt);

        // ---------------- reduce phase (4 threads per pixel) ----------------
        if (gid < NPTS * 4u) {
            const int j = gid >> 2, d0 = (gid & 3) * 8;
            float deg = 0.0f;
#pragma unroll
            for (int sp = 0; sp < KSPLIT; sp++) deg += __ldcg(&g_degp[sp][j]);
            const float inv = ETA / deg;
            const float* X  = out + (size_t)t * FRAME;
            float*       Xn = out + (size_t)(t + 1) * FRAME;
            uint32_t pk[4];
#pragma unroll
            for (int q = 0; q < 4; q++) {
                int d = d0 + q * 2;
                float a0 = 0.0f, a1 = 0.0f;
#pragma unroll
                for (int sp = 0; sp < KSPLIT; sp++) {
                    a0 += __ldcg(&g_accum[sp][d][j]);
                    a1 += __ldcg(&g_accum[sp][d + 1][j]);
                }
                float x0 = a0 * inv + (1.0f - ETA) * X[d * NPTS + j];
                float x1 = a1 * inv + (1.0f - ETA) * X[(d + 1) * NPTS + j];
                Xn[d * NPTS + j] = x0;
                Xn[(d + 1) * NPTS + j] = x1;
                if (t < 2) {
                    g_v[d * NPTS + j] = __float2half(x0);
                    g_v[(d + 1) * NPTS + j] = __float2half(x1);
                    pk[q] = cvt_f16x2(x0 * SCALE, x1 * SCALE);
                }
            }
            if (t < 2)
                *reinterpret_cast<uint4*>(g_s + j * DIM + d0) =
                    make_uint4(pk[0], pk[1], pk[2], pk[3]);
        }
        if (t < 2) { tgt += GRID; grid_bar(tgt); }
    }

    // ---------------- epilogue: counter reset handshake ----------------
    __syncthreads();
    __threadfence();
    if (tid == 0) atomicAdd(&g_fin, 1u);
    if (gid == 0) {
        while (*(volatile unsigned*)&g_fin < GRID) __nanosleep(64);
        *(volatile unsigned*)&g_bar = 0;
        *(volatile unsigned*)&g_fin = 0;
        __threadfence();
    }
}

extern "C" void kernel_launch(void* const* d_in, const int* in_sizes, int n_in,
                              void* d_out, int out_size) {
    const float* x_in = (const float*)d_in[0];
    float* out = (float*)d_out;
    dim3 grid(JT, KSPLIT);
    ms_persist<<<grid, 128>>>(x_in, out);
}